// round 13
// baseline (speedup 1.0000x reference)
#include <cuda_runtime.h>
#include <cuda_fp16.h>
#include <math_constants.h>

#define Nn 50000
#define Dd 128
#define Ee 800000
#define CAP 64
#define LRELU_ALPHA 0.2f

#define GEMM_BLOCKS 148        // one per SM; LUT[bid%148] co-locates b and b+148
#define SCAT_BLOCKS 148
#define SC_THREADS (SCAT_BLOCKS * 128)
#define NTILES 3125            // 50000 / 16
#define RESET_BLOCKS 98        // ceil(Nn/4/128)

// Scratch (device globals -- no allocation allowed)
__device__ __align__(16) __half g_Whh[(size_t)Nn * Dd];  // 12.8 MB, L2-resident
__device__ float g_sv[Nn];
__device__ float g_dv[Nn];
__device__ __align__(16) int g_cnt[Nn];
__device__ int   g_srcs[(size_t)Nn * CAP];               // direct-mapped CSR
__device__ __align__(16) float g_wa[Dd], g_wb[Dd];       // W@a_src, W@a_dst

__device__ __forceinline__ unsigned tf32(float f) {
    unsigned u; asm("cvt.rna.tf32.f32 %0, %1;" : "=r"(u) : "f"(f)); return u;
}
__device__ __forceinline__ void mma_tf32(float c[4], const unsigned a[4], const unsigned b[2]) {
    asm volatile(
        "mma.sync.aligned.m16n8k8.row.col.f32.tf32.tf32.f32 "
        "{%0,%1,%2,%3}, {%4,%5,%6,%7}, {%8,%9}, {%0,%1,%2,%3};"
        : "+f"(c[0]), "+f"(c[1]), "+f"(c[2]), "+f"(c[3])
        : "r"(a[0]), "r"(a[1]), "r"(a[2]), "r"(a[3]), "r"(b[0]), "r"(b[1]));
}
__device__ __forceinline__ float dot4(float4 x, float4 y) {
    return fmaf(x.x, y.x, fmaf(x.y, y.y, fmaf(x.z, y.z, x.w * y.w)));
}

// ---------------------------------------------------------------------------
// K0: zero in-degree counters; one extra block computes wa = W@a_src,
// wb = W@a_dst (reuses the launch -- no extra kernel).
// ---------------------------------------------------------------------------
__global__ void k_reset(const float* __restrict__ W, const float* __restrict__ a) {
    if (blockIdx.x == RESET_BLOCKS) {
        const int k = threadIdx.x;   // 0..127: row of W
        const float4* Wr = (const float4*)(W + k * Dd);
        const float4* av = (const float4*)a;
        const float4* bv = (const float4*)(a + Dd);
        float va = 0.f, vb = 0.f;
#pragma unroll
        for (int j = 0; j < Dd / 4; j++) {
            float4 w4 = Wr[j];
            float4 a4 = av[j], b4 = bv[j];
            va = fmaf(w4.x, a4.x, fmaf(w4.y, a4.y, fmaf(w4.z, a4.z, fmaf(w4.w, a4.w, va))));
            vb = fmaf(w4.x, b4.x, fmaf(w4.y, b4.y, fmaf(w4.z, b4.z, fmaf(w4.w, b4.w, vb))));
        }
        g_wa[k] = va;
        g_wb[k] = vb;
        return;
    }
    int i = blockIdx.x * blockDim.x + threadIdx.x;
    if (i < Nn / 4) ((int4*)g_cnt)[i] = make_int4(0, 0, 0, 0);
}

// ---------------------------------------------------------------------------
// K1: block-role build.
//   bid <  148: persistent tf32-mma gemm, NO epilogue (Wh store only);
//               A-tile software-pipelined, tf32 pre-converted in smem.
//   bid >= 148: CSR scatter, then sv=h@wa / dv=h@wb pass (hidden under gemm).
// ---------------------------------------------------------------------------
__global__ __launch_bounds__(128, 2)
void k_build(const float* __restrict__ h, const float* __restrict__ W,
             const int4* __restrict__ src4, const int4* __restrict__ dst4) {
    if (blockIdx.x >= GEMM_BLOCKS) {
        const int sb = blockIdx.x - GEMM_BLOCKS;
        __shared__ float4 swa[32], swb[32];
        if (threadIdx.x < 32)       swa[threadIdx.x]      = ((const float4*)g_wa)[threadIdx.x];
        else if (threadIdx.x < 64)  swb[threadIdx.x - 32] = ((const float4*)g_wb)[threadIdx.x - 32];
        __syncthreads();

        // ----- scatter: 4 edges per int4, grid-stride -----
        for (int i = sb * 128 + threadIdx.x; i < Ee / 4; i += SC_THREADS) {
            int4 s = src4[i], d = dst4[i];
            int sl;
            sl = atomicAdd(&g_cnt[d.x], 1); if (sl < CAP) g_srcs[d.x * CAP + sl] = s.x;
            sl = atomicAdd(&g_cnt[d.y], 1); if (sl < CAP) g_srcs[d.y * CAP + sl] = s.y;
            sl = atomicAdd(&g_cnt[d.z], 1); if (sl < CAP) g_srcs[d.z * CAP + sl] = s.z;
            sl = atomicAdd(&g_cnt[d.w], 1); if (sl < CAP) g_srcs[d.w * CAP + sl] = s.w;
        }

        // ----- sv/dv pass: warp per row, 2 rows per iteration -----
        const int wid  = threadIdx.x >> 5;
        const int lane = threadIdx.x & 31;
        const int nwarps = SCAT_BLOCKS * 4;   // 592
        const float4 wa4 = swa[lane], wb4 = swb[lane];
        for (int r0 = sb * 4 + wid; r0 < Nn; r0 += 2 * nwarps) {
            const int r1 = r0 + nwarps;
            float4 h0 = ((const float4*)h)[r0 * 32 + lane];
            float s0 = dot4(h0, wa4), d0 = dot4(h0, wb4);
            float s1 = 0.f, d1 = 0.f;
            if (r1 < Nn) {
                float4 h1 = ((const float4*)h)[r1 * 32 + lane];
                s1 = dot4(h1, wa4); d1 = dot4(h1, wb4);
            }
#pragma unroll
            for (int off = 16; off; off >>= 1) {
                s0 += __shfl_down_sync(0xffffffffu, s0, off);
                d0 += __shfl_down_sync(0xffffffffu, d0, off);
                s1 += __shfl_down_sync(0xffffffffu, s1, off);
                d1 += __shfl_down_sync(0xffffffffu, d1, off);
            }
            if (lane == 0) {
                g_sv[r0] = s0; g_dv[r0] = d0;
                if (r1 < Nn) { g_sv[r1] = s1; g_dv[r1] = d1; }
            }
        }
        return;
    }

    // ----- gemm role (pipelined; sh holds tf32 bit patterns; no epilogue) -----
    __shared__ __align__(16) unsigned sh[16][132];
    const int lane  = threadIdx.x & 31;
    const int wn    = threadIdx.x >> 5;
    const int ncol0 = wn * 32;
    const int r     = lane >> 2;
    const int cc    = 2 * (lane & 3);

    unsigned b[16][4][2];
#pragma unroll
    for (int ks = 0; ks < 16; ks++)
#pragma unroll
        for (int j = 0; j < 4; j++) {
            int n  = ncol0 + j * 8 + (lane >> 2);
            int k0 = ks * 8 + (lane & 3);
            b[ks][j][0] = tf32(W[k0 * Dd + n]);
            b[ks][j][1] = tf32(W[(k0 + 4) * Dd + n]);
        }

    // prefetch first tile
    float4 pre[4];
    {
        const float4* hsrc = (const float4*)(h + (size_t)blockIdx.x * 16 * Dd);
#pragma unroll
        for (int t = 0; t < 4; t++) pre[t] = hsrc[threadIdx.x + t * 128];
    }

    for (int tile = blockIdx.x; tile < NTILES; tile += GEMM_BLOCKS) {
        const int base = tile * 16;

#pragma unroll
        for (int t = 0; t < 4; t++) {
            int idx = threadIdx.x + t * 128;
            int rr = idx >> 5, c2 = idx & 31;
            *(uint4*)&sh[rr][c2 * 4] = make_uint4(
                tf32(pre[t].x), tf32(pre[t].y), tf32(pre[t].z), tf32(pre[t].w));
        }
        __syncthreads();

        const int ntile = tile + GEMM_BLOCKS;
        if (ntile < NTILES) {
            const float4* hsrc = (const float4*)(h + (size_t)ntile * 16 * Dd);
#pragma unroll
            for (int t = 0; t < 4; t++) pre[t] = hsrc[threadIdx.x + t * 128];
        }

        float c[4][4];
#pragma unroll
        for (int j = 0; j < 4; j++)
#pragma unroll
            for (int q = 0; q < 4; q++) c[j][q] = 0.0f;

#pragma unroll
        for (int ks = 0; ks < 16; ks++) {
            const int kc = ks * 8 + (lane & 3);
            unsigned av[4];
            av[0] = sh[r][kc];
            av[1] = sh[r + 8][kc];
            av[2] = sh[r][kc + 4];
            av[3] = sh[r + 8][kc + 4];
#pragma unroll
            for (int j = 0; j < 4; j++) mma_tf32(c[j], av, b[ks][j]);
        }

#pragma unroll
        for (int j = 0; j < 4; j++) {
            int col = ncol0 + j * 8 + cc;
            *(__half2*)&g_Whh[(size_t)(base + r) * Dd + col] =
                __floats2half2_rn(c[j][0], c[j][1]);
            *(__half2*)&g_Whh[(size_t)(base + r + 8) * Dd + col] =
                __floats2half2_rn(c[j][2], c[j][3]);
        }
        __syncthreads();   // sh consumed; safe to restage next tile
    }
}

// ---------------------------------------------------------------------------
// K2: fused per-node softmax + aggregation + residual. One warp per node.
// EXACT R5 kernel (measured 27.4us). NO g_cnt write (empirically toxic).
// ---------------------------------------------------------------------------
__global__ __launch_bounds__(256)
void k_node(const float* __restrict__ h, float* __restrict__ out) {
    __shared__ float2 stage[8][CAP];
    const int warp = threadIdx.x >> 5;
    const int lane = threadIdx.x & 31;
    const int v    = blockIdx.x * 8 + warp;
    if (v >= Nn) return;

    float4 acc = ((const float4*)h)[v * 32 + lane];  // residual
    int cnt = g_cnt[v];
    cnt = cnt < CAP ? cnt : CAP;

    if (cnt > 0) {
        const float dvv = g_dv[v];
        const int* sp = g_srcs + v * CAP;

        int s0 = 0, s1 = 0;
        float e0 = -CUDART_INF_F, e1 = -CUDART_INF_F;
        if (lane < cnt) {
            s0 = sp[lane];
            float e = g_sv[s0] + dvv;
            e0 = (e > 0.0f) ? e : LRELU_ALPHA * e;
        }
        if (lane + 32 < cnt) {
            s1 = sp[lane + 32];
            float e = g_sv[s1] + dvv;
            e1 = (e > 0.0f) ? e : LRELU_ALPHA * e;
        }

        float m = fmaxf(e0, e1);
#pragma unroll
        for (int off = 16; off; off >>= 1)
            m = fmaxf(m, __shfl_xor_sync(0xffffffffu, m, off));

        float ex0 = (lane < cnt)      ? __expf(e0 - m) : 0.0f;
        float ex1 = (lane + 32 < cnt) ? __expf(e1 - m) : 0.0f;
        float sum = ex0 + ex1;
#pragma unroll
        for (int off = 16; off; off >>= 1)
            sum += __shfl_xor_sync(0xffffffffu, sum, off);
        const float inv = 1.0f / sum;

        stage[warp][lane]      = make_float2(ex0 * inv, __int_as_float(s0));
        stage[warp][lane + 32] = make_float2(ex1 * inv, __int_as_float(s1));
        __syncwarp();

        const uint2* Whh = (const uint2*)g_Whh;   // 8B = 4 halfs per lane
        int i = 0;
        for (; i + 4 <= cnt; i += 4) {
            float2 p0 = stage[warp][i + 0];
            float2 p1 = stage[warp][i + 1];
            float2 p2 = stage[warp][i + 2];
            float2 p3 = stage[warp][i + 3];
            uint2 u0 = Whh[__float_as_int(p0.y) * 32 + lane];
            uint2 u1 = Whh[__float_as_int(p1.y) * 32 + lane];
            uint2 u2 = Whh[__float_as_int(p2.y) * 32 + lane];
            uint2 u3 = Whh[__float_as_int(p3.y) * 32 + lane];
#define ACC(u, al)                                                         \
            {                                                              \
                float2 lo = __half22float2(*(__half2*)&(u).x);             \
                float2 hi = __half22float2(*(__half2*)&(u).y);             \
                acc.x = fmaf((al), lo.x, acc.x);                           \
                acc.y = fmaf((al), lo.y, acc.y);                           \
                acc.z = fmaf((al), hi.x, acc.z);                           \
                acc.w = fmaf((al), hi.y, acc.w);                           \
            }
            ACC(u0, p0.x) ACC(u1, p1.x) ACC(u2, p2.x) ACC(u3, p3.x)
        }
        for (; i < cnt; i++) {
            float2 p = stage[warp][i];
            uint2 u = Whh[__float_as_int(p.y) * 32 + lane];
            ACC(u, p.x)
        }
#undef ACC
    }

    ((float4*)out)[v * 32 + lane] = acc;
}

// ---------------------------------------------------------------------------
extern "C" void kernel_launch(void* const* d_in, const int* in_sizes, int n_in,
                              void* d_out, int out_size) {
    const float* h   = (const float*)d_in[0];
    const float* W   = (const float*)d_in[1];
    const float* a   = (const float*)d_in[2];
    const int*   src = (const int*)d_in[3];
    const int*   dst = (const int*)d_in[4];
    float*       out = (float*)d_out;

    k_reset<<<RESET_BLOCKS + 1, 128>>>(W, a);
    k_build<<<GEMM_BLOCKS + SCAT_BLOCKS, 128>>>(h, W,
                                                (const int4*)src, (const int4*)dst);
    k_node <<<(Nn + 7) / 8, 256>>>(h, out);
}

// round 14
// speedup vs baseline: 1.3785x; 1.3785x over previous
#include <cuda_runtime.h>
#include <cuda_fp16.h>
#include <math_constants.h>

#define Nn 50000
#define Dd 128
#define Ee 800000
#define CAP 64
#define LRELU_ALPHA 0.2f

#define GEMM_BLOCKS 148        // one per SM; LUT[bid%148] co-locates b and b+148
#define SCAT_BLOCKS 148
#define SC_THREADS (SCAT_BLOCKS * 128)
#define NTILES 3125            // 50000 / 16

// Scratch (device globals -- no allocation allowed)
__device__ __align__(16) __half g_Whh[(size_t)Nn * Dd];  // 12.8 MB, L2-resident
__device__ float g_sv[Nn];
__device__ float g_dv[Nn];
__device__ __align__(16) int g_cnt[Nn];
__device__ int   g_srcs[(size_t)Nn * CAP];               // direct-mapped CSR

__device__ __forceinline__ unsigned tf32(float f) {
    unsigned u; asm("cvt.rna.tf32.f32 %0, %1;" : "=r"(u) : "f"(f)); return u;
}
__device__ __forceinline__ void mma_tf32(float c[4], const unsigned a[4], const unsigned b[2]) {
    asm volatile(
        "mma.sync.aligned.m16n8k8.row.col.f32.tf32.tf32.f32 "
        "{%0,%1,%2,%3}, {%4,%5,%6,%7}, {%8,%9}, {%0,%1,%2,%3};"
        : "+f"(c[0]), "+f"(c[1]), "+f"(c[2]), "+f"(c[3])
        : "r"(a[0]), "r"(a[1]), "r"(a[2]), "r"(a[3]), "r"(b[0]), "r"(b[1]));
}

// ---------------------------------------------------------------------------
// K0: zero in-degree counters (separate kernel -- folding elsewhere is toxic:
// R6/R7/R9 into k_node, R11 barrier, R13 combined-reset all regressed).
// ---------------------------------------------------------------------------
__global__ void k_reset() {
    int i = blockIdx.x * blockDim.x + threadIdx.x;
    if (i < Nn / 4) ((int4*)g_cnt)[i] = make_int4(0, 0, 0, 0);
}

// ---------------------------------------------------------------------------
// K1: block-role build (R12 structure).
//   bid <  148: persistent tf32-mma gemm; pipelined A-tile; tf32 bits in smem;
//               sv/dv fused epilogue; accumulators SPLIT even/odd ks -> 8
//               independent HMMA chains (halves dependency latency).
//   bid >= 148: grid-stride CSR scatter (hidden under gemm on the same SM).
// ---------------------------------------------------------------------------
__global__ __launch_bounds__(128, 2)
void k_build(const float* __restrict__ h, const float* __restrict__ W,
             const float* __restrict__ a,
             const int4* __restrict__ src4, const int4* __restrict__ dst4) {
    if (blockIdx.x >= GEMM_BLOCKS) {
        // ----- scatter role: 4 edges per int4, grid-stride -----
        for (int i = (blockIdx.x - GEMM_BLOCKS) * 128 + threadIdx.x;
             i < Ee / 4; i += SC_THREADS) {
            int4 s = src4[i], d = dst4[i];
            int sl;
            sl = atomicAdd(&g_cnt[d.x], 1); if (sl < CAP) g_srcs[d.x * CAP + sl] = s.x;
            sl = atomicAdd(&g_cnt[d.y], 1); if (sl < CAP) g_srcs[d.y * CAP + sl] = s.y;
            sl = atomicAdd(&g_cnt[d.z], 1); if (sl < CAP) g_srcs[d.z * CAP + sl] = s.z;
            sl = atomicAdd(&g_cnt[d.w], 1); if (sl < CAP) g_srcs[d.w * CAP + sl] = s.w;
        }
        return;
    }

    // ----- gemm role -----
    __shared__ __align__(16) unsigned sh[16][132];
    __shared__ float ssv[4][16], sdv[4][16];
    const int lane  = threadIdx.x & 31;
    const int wn    = threadIdx.x >> 5;
    const int ncol0 = wn * 32;
    const int r     = lane >> 2;
    const int cc    = 2 * (lane & 3);

    unsigned b[16][4][2];
#pragma unroll
    for (int ks = 0; ks < 16; ks++)
#pragma unroll
        for (int j = 0; j < 4; j++) {
            int n  = ncol0 + j * 8 + (lane >> 2);
            int k0 = ks * 8 + (lane & 3);
            b[ks][j][0] = tf32(W[k0 * Dd + n]);
            b[ks][j][1] = tf32(W[(k0 + 4) * Dd + n]);
        }
    float2 as[4], ad[4];
#pragma unroll
    for (int j = 0; j < 4; j++) {
        int col = ncol0 + j * 8 + cc;
        as[j] = make_float2(a[col], a[col + 1]);
        ad[j] = make_float2(a[Dd + col], a[Dd + col + 1]);
    }

    // prefetch first tile
    float4 pre[4];
    {
        const float4* hsrc = (const float4*)(h + (size_t)blockIdx.x * 16 * Dd);
#pragma unroll
        for (int t = 0; t < 4; t++) pre[t] = hsrc[threadIdx.x + t * 128];
    }

    for (int tile = blockIdx.x; tile < NTILES; tile += GEMM_BLOCKS) {
        const int base = tile * 16;

#pragma unroll
        for (int t = 0; t < 4; t++) {
            int idx = threadIdx.x + t * 128;
            int rr = idx >> 5, c2 = idx & 31;
            *(uint4*)&sh[rr][c2 * 4] = make_uint4(
                tf32(pre[t].x), tf32(pre[t].y), tf32(pre[t].z), tf32(pre[t].w));
        }
        __syncthreads();

        const int ntile = tile + GEMM_BLOCKS;
        if (ntile < NTILES) {
            const float4* hsrc = (const float4*)(h + (size_t)ntile * 16 * Dd);
#pragma unroll
            for (int t = 0; t < 4; t++) pre[t] = hsrc[threadIdx.x + t * 128];
        }

        // dual accumulators: even/odd ks chains (8 independent HMMA chains)
        float ce[4][4], co[4][4];
#pragma unroll
        for (int j = 0; j < 4; j++)
#pragma unroll
            for (int q = 0; q < 4; q++) { ce[j][q] = 0.0f; co[j][q] = 0.0f; }

#pragma unroll
        for (int ks = 0; ks < 16; ks += 2) {
            const int kc0 = ks * 8 + (lane & 3);
            const int kc1 = kc0 + 8;
            unsigned av0[4], av1[4];
            av0[0] = sh[r][kc0];     av1[0] = sh[r][kc1];
            av0[1] = sh[r + 8][kc0]; av1[1] = sh[r + 8][kc1];
            av0[2] = sh[r][kc0 + 4]; av1[2] = sh[r][kc1 + 4];
            av0[3] = sh[r + 8][kc0 + 4]; av1[3] = sh[r + 8][kc1 + 4];
#pragma unroll
            for (int j = 0; j < 4; j++) {
                mma_tf32(ce[j], av0, b[ks][j]);
                mma_tf32(co[j], av1, b[ks + 1][j]);
            }
        }

        float vs0 = 0.f, vs1 = 0.f, vd0 = 0.f, vd1 = 0.f;
#pragma unroll
        for (int j = 0; j < 4; j++) {
            float c0 = ce[j][0] + co[j][0];
            float c1 = ce[j][1] + co[j][1];
            float c2 = ce[j][2] + co[j][2];
            float c3 = ce[j][3] + co[j][3];
            int col = ncol0 + j * 8 + cc;
            *(__half2*)&g_Whh[(size_t)(base + r) * Dd + col] =
                __floats2half2_rn(c0, c1);
            *(__half2*)&g_Whh[(size_t)(base + r + 8) * Dd + col] =
                __floats2half2_rn(c2, c3);
            vs0 = fmaf(c0, as[j].x, fmaf(c1, as[j].y, vs0));
            vs1 = fmaf(c2, as[j].x, fmaf(c3, as[j].y, vs1));
            vd0 = fmaf(c0, ad[j].x, fmaf(c1, ad[j].y, vd0));
            vd1 = fmaf(c2, ad[j].x, fmaf(c3, ad[j].y, vd1));
        }
#pragma unroll
        for (int off = 1; off <= 2; off <<= 1) {
            vs0 += __shfl_xor_sync(0xffffffffu, vs0, off);
            vs1 += __shfl_xor_sync(0xffffffffu, vs1, off);
            vd0 += __shfl_xor_sync(0xffffffffu, vd0, off);
            vd1 += __shfl_xor_sync(0xffffffffu, vd1, off);
        }
        if ((lane & 3) == 0) {
            ssv[wn][r] = vs0; ssv[wn][r + 8] = vs1;
            sdv[wn][r] = vd0; sdv[wn][r + 8] = vd1;
        }
        __syncthreads();
        if (threadIdx.x < 16) {
            int t = threadIdx.x;
            g_sv[base + t] = ssv[0][t] + ssv[1][t] + ssv[2][t] + ssv[3][t];
        } else if (threadIdx.x >= 32 && threadIdx.x < 48) {
            int t = threadIdx.x - 32;
            g_dv[base + t] = sdv[0][t] + sdv[1][t] + sdv[2][t] + sdv[3][t];
        }
    }
}

// ---------------------------------------------------------------------------
// K2: fused per-node softmax + aggregation + residual. One warp per node.
// EXACT R5 kernel (measured 27.4us). NO g_cnt write (empirically toxic).
// ---------------------------------------------------------------------------
__global__ __launch_bounds__(256)
void k_node(const float* __restrict__ h, float* __restrict__ out) {
    __shared__ float2 stage[8][CAP];
    const int warp = threadIdx.x >> 5;
    const int lane = threadIdx.x & 31;
    const int v    = blockIdx.x * 8 + warp;
    if (v >= Nn) return;

    float4 acc = ((const float4*)h)[v * 32 + lane];  // residual
    int cnt = g_cnt[v];
    cnt = cnt < CAP ? cnt : CAP;

    if (cnt > 0) {
        const float dvv = g_dv[v];
        const int* sp = g_srcs + v * CAP;

        int s0 = 0, s1 = 0;
        float e0 = -CUDART_INF_F, e1 = -CUDART_INF_F;
        if (lane < cnt) {
            s0 = sp[lane];
            float e = g_sv[s0] + dvv;
            e0 = (e > 0.0f) ? e : LRELU_ALPHA * e;
        }
        if (lane + 32 < cnt) {
            s1 = sp[lane + 32];
            float e = g_sv[s1] + dvv;
            e1 = (e > 0.0f) ? e : LRELU_ALPHA * e;
        }

        float m = fmaxf(e0, e1);
#pragma unroll
        for (int off = 16; off; off >>= 1)
            m = fmaxf(m, __shfl_xor_sync(0xffffffffu, m, off));

        float ex0 = (lane < cnt)      ? __expf(e0 - m) : 0.0f;
        float ex1 = (lane + 32 < cnt) ? __expf(e1 - m) : 0.0f;
        float sum = ex0 + ex1;
#pragma unroll
        for (int off = 16; off; off >>= 1)
            sum += __shfl_xor_sync(0xffffffffu, sum, off);
        const float inv = 1.0f / sum;

        stage[warp][lane]      = make_float2(ex0 * inv, __int_as_float(s0));
        stage[warp][lane + 32] = make_float2(ex1 * inv, __int_as_float(s1));
        __syncwarp();

        const uint2* Whh = (const uint2*)g_Whh;   // 8B = 4 halfs per lane
        int i = 0;
        for (; i + 4 <= cnt; i += 4) {
            float2 p0 = stage[warp][i + 0];
            float2 p1 = stage[warp][i + 1];
            float2 p2 = stage[warp][i + 2];
            float2 p3 = stage[warp][i + 3];
            uint2 u0 = Whh[__float_as_int(p0.y) * 32 + lane];
            uint2 u1 = Whh[__float_as_int(p1.y) * 32 + lane];
            uint2 u2 = Whh[__float_as_int(p2.y) * 32 + lane];
            uint2 u3 = Whh[__float_as_int(p3.y) * 32 + lane];
#define ACC(u, al)                                                         \
            {                                                              \
                float2 lo = __half22float2(*(__half2*)&(u).x);             \
                float2 hi = __half22float2(*(__half2*)&(u).y);             \
                acc.x = fmaf((al), lo.x, acc.x);                           \
                acc.y = fmaf((al), lo.y, acc.y);                           \
                acc.z = fmaf((al), hi.x, acc.z);                           \
                acc.w = fmaf((al), hi.y, acc.w);                           \
            }
            ACC(u0, p0.x) ACC(u1, p1.x) ACC(u2, p2.x) ACC(u3, p3.x)
        }
        for (; i < cnt; i++) {
            float2 p = stage[warp][i];
            uint2 u = Whh[__float_as_int(p.y) * 32 + lane];
            ACC(u, p.x)
        }
#undef ACC
    }

    ((float4*)out)[v * 32 + lane] = acc;
}

// ---------------------------------------------------------------------------
extern "C" void kernel_launch(void* const* d_in, const int* in_sizes, int n_in,
                              void* d_out, int out_size) {
    const float* h   = (const float*)d_in[0];
    const float* W   = (const float*)d_in[1];
    const float* a   = (const float*)d_in[2];
    const int*   src = (const int*)d_in[3];
    const int*   dst = (const int*)d_in[4];
    float*       out = (float*)d_out;

    k_reset<<<(Nn / 4 + 127) / 128, 128>>>();
    k_build<<<GEMM_BLOCKS + SCAT_BLOCKS, 128>>>(h, W, a,
                                                (const int4*)src, (const int4*)dst);
    k_node <<<(Nn + 7) / 8, 256>>>(h, out);
}

// round 15
// speedup vs baseline: 1.4179x; 1.0286x over previous
#include <cuda_runtime.h>
#include <cuda_fp16.h>
#include <math_constants.h>

#define Nn 50000
#define Dd 128
#define Ee 800000
#define CAP 64
#define LRELU_ALPHA 0.2f

#define GEMM_BLOCKS 296        // two per SM (blocks b, b+148 share an SM)
#define SCAT_BLOCKS 148        // one per SM (blocks 296..443 -> SM bid-296)
#define SC_THREADS (SCAT_BLOCKS * 128)
#define NTILES 3125            // 50000 / 16

// Scratch (device globals -- no allocation allowed)
__device__ __align__(16) __half g_Whh[(size_t)Nn * Dd];  // 12.8 MB, L2-resident
__device__ float g_sv[Nn];
__device__ float g_dv[Nn];
__device__ __align__(16) int g_cnt[Nn];
__device__ int   g_srcs[(size_t)Nn * CAP];               // direct-mapped CSR

__device__ __forceinline__ unsigned tf32(float f) {
    unsigned u; asm("cvt.rna.tf32.f32 %0, %1;" : "=r"(u) : "f"(f)); return u;
}
__device__ __forceinline__ void mma_tf32(float c[4], const unsigned a[4], const unsigned b[2]) {
    asm volatile(
        "mma.sync.aligned.m16n8k8.row.col.f32.tf32.tf32.f32 "
        "{%0,%1,%2,%3}, {%4,%5,%6,%7}, {%8,%9}, {%0,%1,%2,%3};"
        : "+f"(c[0]), "+f"(c[1]), "+f"(c[2]), "+f"(c[3])
        : "r"(a[0]), "r"(a[1]), "r"(a[2]), "r"(a[3]), "r"(b[0]), "r"(b[1]));
}

// ---------------------------------------------------------------------------
// K0: zero in-degree counters (separate kernel -- folding elsewhere is toxic:
// R6/R7/R9 into k_node, R11 barrier, R13 combined-reset all regressed).
// ---------------------------------------------------------------------------
__global__ void k_reset() {
    int i = blockIdx.x * blockDim.x + threadIdx.x;
    if (i < Nn / 4) ((int4*)g_cnt)[i] = make_int4(0, 0, 0, 0);
}

// ---------------------------------------------------------------------------
// K1: block-role build at occupancy 3.
//   bid < 296:  persistent tf32-mma gemm, 2 blocks/SM -> 2 warps/SMSP fill
//               the issue gaps (R8 evidence: ~14.3us full-chip at this occ).
//               No reg-prefetch (the sibling warp hides load latency);
//               cvt-hoisted tf32 staging; sv/dv fused epilogue (R12 numerics).
//   bid >= 296: grid-stride CSR scatter (1 block/SM, hidden under gemm).
// ---------------------------------------------------------------------------
__global__ __launch_bounds__(128, 3)
void k_build(const float* __restrict__ h, const float* __restrict__ W,
             const float* __restrict__ a,
             const int4* __restrict__ src4, const int4* __restrict__ dst4) {
    if (blockIdx.x >= GEMM_BLOCKS) {
        // ----- scatter role: 4 edges per int4, grid-stride -----
        for (int i = (blockIdx.x - GEMM_BLOCKS) * 128 + threadIdx.x;
             i < Ee / 4; i += SC_THREADS) {
            int4 s = src4[i], d = dst4[i];
            int sl;
            sl = atomicAdd(&g_cnt[d.x], 1); if (sl < CAP) g_srcs[d.x * CAP + sl] = s.x;
            sl = atomicAdd(&g_cnt[d.y], 1); if (sl < CAP) g_srcs[d.y * CAP + sl] = s.y;
            sl = atomicAdd(&g_cnt[d.z], 1); if (sl < CAP) g_srcs[d.z * CAP + sl] = s.z;
            sl = atomicAdd(&g_cnt[d.w], 1); if (sl < CAP) g_srcs[d.w * CAP + sl] = s.w;
        }
        return;
    }

    // ----- gemm role -----
    __shared__ __align__(16) unsigned sh[16][132];
    __shared__ float ssv[4][16], sdv[4][16];
    const int lane  = threadIdx.x & 31;
    const int wn    = threadIdx.x >> 5;
    const int ncol0 = wn * 32;
    const int r     = lane >> 2;
    const int cc    = 2 * (lane & 3);

    unsigned b[16][4][2];
#pragma unroll
    for (int ks = 0; ks < 16; ks++)
#pragma unroll
        for (int j = 0; j < 4; j++) {
            int n  = ncol0 + j * 8 + (lane >> 2);
            int k0 = ks * 8 + (lane & 3);
            b[ks][j][0] = tf32(W[k0 * Dd + n]);
            b[ks][j][1] = tf32(W[(k0 + 4) * Dd + n]);
        }
    float2 as[4], ad[4];
#pragma unroll
    for (int j = 0; j < 4; j++) {
        int col = ncol0 + j * 8 + cc;
        as[j] = make_float2(a[col], a[col + 1]);
        ad[j] = make_float2(a[Dd + col], a[Dd + col + 1]);
    }

    for (int tile = blockIdx.x; tile < NTILES; tile += GEMM_BLOCKS) {
        const int base = tile * 16;

        // cooperative tile load with tf32 pre-conversion
        const float4* hsrc = (const float4*)(h + (size_t)base * Dd);
#pragma unroll
        for (int t = 0; t < 4; t++) {
            int idx = threadIdx.x + t * 128;
            int rr = idx >> 5, c2 = idx & 31;
            float4 v = hsrc[idx];
            *(uint4*)&sh[rr][c2 * 4] = make_uint4(
                tf32(v.x), tf32(v.y), tf32(v.z), tf32(v.w));
        }
        __syncthreads();

        float c[4][4];
#pragma unroll
        for (int j = 0; j < 4; j++)
#pragma unroll
            for (int q = 0; q < 4; q++) c[j][q] = 0.0f;

#pragma unroll
        for (int ks = 0; ks < 16; ks++) {
            const int kc = ks * 8 + (lane & 3);
            unsigned av[4];
            av[0] = sh[r][kc];
            av[1] = sh[r + 8][kc];
            av[2] = sh[r][kc + 4];
            av[3] = sh[r + 8][kc + 4];
#pragma unroll
            for (int j = 0; j < 4; j++) mma_tf32(c[j], av, b[ks][j]);
        }

        float vs0 = 0.f, vs1 = 0.f, vd0 = 0.f, vd1 = 0.f;
#pragma unroll
        for (int j = 0; j < 4; j++) {
            int col = ncol0 + j * 8 + cc;
            *(__half2*)&g_Whh[(size_t)(base + r) * Dd + col] =
                __floats2half2_rn(c[j][0], c[j][1]);
            *(__half2*)&g_Whh[(size_t)(base + r + 8) * Dd + col] =
                __floats2half2_rn(c[j][2], c[j][3]);
            vs0 = fmaf(c[j][0], as[j].x, fmaf(c[j][1], as[j].y, vs0));
            vs1 = fmaf(c[j][2], as[j].x, fmaf(c[j][3], as[j].y, vs1));
            vd0 = fmaf(c[j][0], ad[j].x, fmaf(c[j][1], ad[j].y, vd0));
            vd1 = fmaf(c[j][2], ad[j].x, fmaf(c[j][3], ad[j].y, vd1));
        }
#pragma unroll
        for (int off = 1; off <= 2; off <<= 1) {
            vs0 += __shfl_xor_sync(0xffffffffu, vs0, off);
            vs1 += __shfl_xor_sync(0xffffffffu, vs1, off);
            vd0 += __shfl_xor_sync(0xffffffffu, vd0, off);
            vd1 += __shfl_xor_sync(0xffffffffu, vd1, off);
        }
        if ((lane & 3) == 0) {
            ssv[wn][r] = vs0; ssv[wn][r + 8] = vs1;
            sdv[wn][r] = vd0; sdv[wn][r + 8] = vd1;
        }
        __syncthreads();
        if (threadIdx.x < 16) {
            int t = threadIdx.x;
            g_sv[base + t] = ssv[0][t] + ssv[1][t] + ssv[2][t] + ssv[3][t];
        } else if (threadIdx.x >= 32 && threadIdx.x < 48) {
            int t = threadIdx.x - 32;
            g_dv[base + t] = sdv[0][t] + sdv[1][t] + sdv[2][t] + sdv[3][t];
        }
    }
}

// ---------------------------------------------------------------------------
// K2: fused per-node softmax + aggregation + residual. One warp per node.
// EXACT R5 kernel (measured 27.4us). NO g_cnt write (empirically toxic).
// ---------------------------------------------------------------------------
__global__ __launch_bounds__(256)
void k_node(const float* __restrict__ h, float* __restrict__ out) {
    __shared__ float2 stage[8][CAP];
    const int warp = threadIdx.x >> 5;
    const int lane = threadIdx.x & 31;
    const int v    = blockIdx.x * 8 + warp;
    if (v >= Nn) return;

    float4 acc = ((const float4*)h)[v * 32 + lane];  // residual
    int cnt = g_cnt[v];
    cnt = cnt < CAP ? cnt : CAP;

    if (cnt > 0) {
        const float dvv = g_dv[v];
        const int* sp = g_srcs + v * CAP;

        int s0 = 0, s1 = 0;
        float e0 = -CUDART_INF_F, e1 = -CUDART_INF_F;
        if (lane < cnt) {
            s0 = sp[lane];
            float e = g_sv[s0] + dvv;
            e0 = (e > 0.0f) ? e : LRELU_ALPHA * e;
        }
        if (lane + 32 < cnt) {
            s1 = sp[lane + 32];
            float e = g_sv[s1] + dvv;
            e1 = (e > 0.0f) ? e : LRELU_ALPHA * e;
        }

        float m = fmaxf(e0, e1);
#pragma unroll
        for (int off = 16; off; off >>= 1)
            m = fmaxf(m, __shfl_xor_sync(0xffffffffu, m, off));

        float ex0 = (lane < cnt)      ? __expf(e0 - m) : 0.0f;
        float ex1 = (lane + 32 < cnt) ? __expf(e1 - m) : 0.0f;
        float sum = ex0 + ex1;
#pragma unroll
        for (int off = 16; off; off >>= 1)
            sum += __shfl_xor_sync(0xffffffffu, sum, off);
        const float inv = 1.0f / sum;

        stage[warp][lane]      = make_float2(ex0 * inv, __int_as_float(s0));
        stage[warp][lane + 32] = make_float2(ex1 * inv, __int_as_float(s1));
        __syncwarp();

        const uint2* Whh = (const uint2*)g_Whh;   // 8B = 4 halfs per lane
        int i = 0;
        for (; i + 4 <= cnt; i += 4) {
            float2 p0 = stage[warp][i + 0];
            float2 p1 = stage[warp][i + 1];
            float2 p2 = stage[warp][i + 2];
            float2 p3 = stage[warp][i + 3];
            uint2 u0 = Whh[__float_as_int(p0.y) * 32 + lane];
            uint2 u1 = Whh[__float_as_int(p1.y) * 32 + lane];
            uint2 u2 = Whh[__float_as_int(p2.y) * 32 + lane];
            uint2 u3 = Whh[__float_as_int(p3.y) * 32 + lane];
#define ACC(u, al)                                                         \
            {                                                              \
                float2 lo = __half22float2(*(__half2*)&(u).x);             \
                float2 hi = __half22float2(*(__half2*)&(u).y);             \
                acc.x = fmaf((al), lo.x, acc.x);                           \
                acc.y = fmaf((al), lo.y, acc.y);                           \
                acc.z = fmaf((al), hi.x, acc.z);                           \
                acc.w = fmaf((al), hi.y, acc.w);                           \
            }
            ACC(u0, p0.x) ACC(u1, p1.x) ACC(u2, p2.x) ACC(u3, p3.x)
        }
        for (; i < cnt; i++) {
            float2 p = stage[warp][i];
            uint2 u = Whh[__float_as_int(p.y) * 32 + lane];
            ACC(u, p.x)
        }
#undef ACC
    }

    ((float4*)out)[v * 32 + lane] = acc;
}

// ---------------------------------------------------------------------------
extern "C" void kernel_launch(void* const* d_in, const int* in_sizes, int n_in,
                              void* d_out, int out_size) {
    const float* h   = (const float*)d_in[0];
    const float* W   = (const float*)d_in[1];
    const float* a   = (const float*)d_in[2];
    const int*   src = (const int*)d_in[3];
    const int*   dst = (const int*)d_in[4];
    float*       out = (float*)d_out;

    k_reset<<<(Nn / 4 + 127) / 128, 128>>>();
    k_build<<<GEMM_BLOCKS + SCAT_BLOCKS, 128>>>(h, W, a,
                                                (const int4*)src, (const int4*)dst);
    k_node <<<(Nn + 7) / 8, 256>>>(h, out);
}

// round 16
// speedup vs baseline: 1.5358x; 1.0832x over previous
#include <cuda_runtime.h>
#include <cuda_fp16.h>
#include <math_constants.h>

#define Nn 50000
#define Dd 128
#define Ee 800000
#define CAP 64
#define LRELU_ALPHA 0.2f

#define GEMM_BLOCKS 148        // one 256-thr gemm block per SM
#define SCAT_BLOCKS 148        // one 256-thr scatter block per SM (b+148 -> SM b)
#define SC_THREADS (SCAT_BLOCKS * 256)
#define NTILES 3125            // 50000 / 16

// Scratch (device globals -- no allocation allowed)
__device__ __align__(16) __half g_Whh[(size_t)Nn * Dd];  // 12.8 MB, L2-resident
__device__ float g_sv[Nn];
__device__ float g_dv[Nn];
__device__ __align__(16) int g_cnt[Nn];
__device__ int   g_srcs[(size_t)Nn * CAP];               // direct-mapped CSR

__device__ __forceinline__ unsigned tf32(float f) {
    unsigned u; asm("cvt.rna.tf32.f32 %0, %1;" : "=r"(u) : "f"(f)); return u;
}
__device__ __forceinline__ void mma_tf32(float c[4], const unsigned a[4], const unsigned b[2]) {
    asm volatile(
        "mma.sync.aligned.m16n8k8.row.col.f32.tf32.tf32.f32 "
        "{%0,%1,%2,%3}, {%4,%5,%6,%7}, {%8,%9}, {%0,%1,%2,%3};"
        : "+f"(c[0]), "+f"(c[1]), "+f"(c[2]), "+f"(c[3])
        : "r"(a[0]), "r"(a[1]), "r"(a[2]), "r"(a[3]), "r"(b[0]), "r"(b[1]));
}

// ---------------------------------------------------------------------------
// K0: zero in-degree counters (separate kernel -- folding elsewhere is toxic:
// R6/R7/R9 into k_node, R11 barrier, R13 combined-reset all regressed).
// ---------------------------------------------------------------------------
__global__ void k_reset() {
    int i = blockIdx.x * blockDim.x + threadIdx.x;
    if (i < Nn / 4) ((int4*)g_cnt)[i] = make_int4(0, 0, 0, 0);
}

// ---------------------------------------------------------------------------
// K1: block-role build, 256-thread blocks.
//   bid < 148:  persistent tf32-mma gemm, 8 warps x 16 output columns each.
//               B frags = 64 regs/thread -> fits (256,2) 128-reg cap, NO
//               spill, 2 gemm warps per SMSP (the R8 operating point).
//               Pipelined A-tile (2 float4/thread); tf32 bits in smem;
//               sv/dv fused epilogue (8-warp reduce).
//   bid >= 148: grid-stride CSR scatter (256 thr; hidden under gemm).
// ---------------------------------------------------------------------------
__global__ __launch_bounds__(256, 2)
void k_build(const float* __restrict__ h, const float* __restrict__ W,
             const float* __restrict__ a,
             const int4* __restrict__ src4, const int4* __restrict__ dst4) {
    if (blockIdx.x >= GEMM_BLOCKS) {
        // ----- scatter role: 4 edges per int4, grid-stride -----
        for (int i = (blockIdx.x - GEMM_BLOCKS) * 256 + threadIdx.x;
             i < Ee / 4; i += SC_THREADS) {
            int4 s = src4[i], d = dst4[i];
            int sl;
            sl = atomicAdd(&g_cnt[d.x], 1); if (sl < CAP) g_srcs[d.x * CAP + sl] = s.x;
            sl = atomicAdd(&g_cnt[d.y], 1); if (sl < CAP) g_srcs[d.y * CAP + sl] = s.y;
            sl = atomicAdd(&g_cnt[d.z], 1); if (sl < CAP) g_srcs[d.z * CAP + sl] = s.z;
            sl = atomicAdd(&g_cnt[d.w], 1); if (sl < CAP) g_srcs[d.w * CAP + sl] = s.w;
        }
        return;
    }

    // ----- gemm role: 8 warps, 16 columns per warp -----
    __shared__ __align__(16) unsigned sh[16][132];
    __shared__ float ssv[8][16], sdv[8][16];
    const int lane  = threadIdx.x & 31;
    const int wn    = threadIdx.x >> 5;          // 0..7
    const int ncol0 = wn * 16;
    const int r     = lane >> 2;
    const int cc    = 2 * (lane & 3);

    // B fragments: 16 ks x 2 j x 2 = 64 regs
    unsigned b[16][2][2];
#pragma unroll
    for (int ks = 0; ks < 16; ks++)
#pragma unroll
        for (int j = 0; j < 2; j++) {
            int n  = ncol0 + j * 8 + (lane >> 2);
            int k0 = ks * 8 + (lane & 3);
            b[ks][j][0] = tf32(W[k0 * Dd + n]);
            b[ks][j][1] = tf32(W[(k0 + 4) * Dd + n]);
        }
    float2 as[2], ad[2];
#pragma unroll
    for (int j = 0; j < 2; j++) {
        int col = ncol0 + j * 8 + cc;
        as[j] = make_float2(a[col], a[col + 1]);
        ad[j] = make_float2(a[Dd + col], a[Dd + col + 1]);
    }

    // prefetch first tile (2 float4 per thread)
    float4 pre[2];
    {
        const float4* hsrc = (const float4*)(h + (size_t)blockIdx.x * 16 * Dd);
#pragma unroll
        for (int t = 0; t < 2; t++) pre[t] = hsrc[threadIdx.x + t * 256];
    }

    for (int tile = blockIdx.x; tile < NTILES; tile += GEMM_BLOCKS) {
        const int base = tile * 16;

#pragma unroll
        for (int t = 0; t < 2; t++) {
            int idx = threadIdx.x + t * 256;
            int rr = idx >> 5, c2 = idx & 31;
            *(uint4*)&sh[rr][c2 * 4] = make_uint4(
                tf32(pre[t].x), tf32(pre[t].y), tf32(pre[t].z), tf32(pre[t].w));
        }
        __syncthreads();

        const int ntile = tile + GEMM_BLOCKS;
        if (ntile < NTILES) {
            const float4* hsrc = (const float4*)(h + (size_t)ntile * 16 * Dd);
#pragma unroll
            for (int t = 0; t < 2; t++) pre[t] = hsrc[threadIdx.x + t * 256];
        }

        float c[2][4];
#pragma unroll
        for (int j = 0; j < 2; j++)
#pragma unroll
            for (int q = 0; q < 4; q++) c[j][q] = 0.0f;

#pragma unroll
        for (int ks = 0; ks < 16; ks++) {
            const int kc = ks * 8 + (lane & 3);
            unsigned av[4];
            av[0] = sh[r][kc];
            av[1] = sh[r + 8][kc];
            av[2] = sh[r][kc + 4];
            av[3] = sh[r + 8][kc + 4];
#pragma unroll
            for (int j = 0; j < 2; j++) mma_tf32(c[j], av, b[ks][j]);
        }

        float vs0 = 0.f, vs1 = 0.f, vd0 = 0.f, vd1 = 0.f;
#pragma unroll
        for (int j = 0; j < 2; j++) {
            int col = ncol0 + j * 8 + cc;
            *(__half2*)&g_Whh[(size_t)(base + r) * Dd + col] =
                __floats2half2_rn(c[j][0], c[j][1]);
            *(__half2*)&g_Whh[(size_t)(base + r + 8) * Dd + col] =
                __floats2half2_rn(c[j][2], c[j][3]);
            vs0 = fmaf(c[j][0], as[j].x, fmaf(c[j][1], as[j].y, vs0));
            vs1 = fmaf(c[j][2], as[j].x, fmaf(c[j][3], as[j].y, vs1));
            vd0 = fmaf(c[j][0], ad[j].x, fmaf(c[j][1], ad[j].y, vd0));
            vd1 = fmaf(c[j][2], ad[j].x, fmaf(c[j][3], ad[j].y, vd1));
        }
#pragma unroll
        for (int off = 1; off <= 2; off <<= 1) {
            vs0 += __shfl_xor_sync(0xffffffffu, vs0, off);
            vs1 += __shfl_xor_sync(0xffffffffu, vs1, off);
            vd0 += __shfl_xor_sync(0xffffffffu, vd0, off);
            vd1 += __shfl_xor_sync(0xffffffffu, vd1, off);
        }
        if ((lane & 3) == 0) {
            ssv[wn][r] = vs0; ssv[wn][r + 8] = vs1;
            sdv[wn][r] = vd0; sdv[wn][r + 8] = vd1;
        }
        __syncthreads();
        if (threadIdx.x < 16) {
            int t = threadIdx.x;
            g_sv[base + t] = ((ssv[0][t] + ssv[1][t]) + (ssv[2][t] + ssv[3][t]))
                           + ((ssv[4][t] + ssv[5][t]) + (ssv[6][t] + ssv[7][t]));
        } else if (threadIdx.x >= 32 && threadIdx.x < 48) {
            int t = threadIdx.x - 32;
            g_dv[base + t] = ((sdv[0][t] + sdv[1][t]) + (sdv[2][t] + sdv[3][t]))
                           + ((sdv[4][t] + sdv[5][t]) + (sdv[6][t] + sdv[7][t]));
        }
    }
}

// ---------------------------------------------------------------------------
// K2: fused per-node softmax + aggregation + residual. One warp per node.
// EXACT R5 kernel (measured 27.4us). NO g_cnt write (empirically toxic).
// ---------------------------------------------------------------------------
__global__ __launch_bounds__(256)
void k_node(const float* __restrict__ h, float* __restrict__ out) {
    __shared__ float2 stage[8][CAP];
    const int warp = threadIdx.x >> 5;
    const int lane = threadIdx.x & 31;
    const int v    = blockIdx.x * 8 + warp;
    if (v >= Nn) return;

    float4 acc = ((const float4*)h)[v * 32 + lane];  // residual
    int cnt = g_cnt[v];
    cnt = cnt < CAP ? cnt : CAP;

    if (cnt > 0) {
        const float dvv = g_dv[v];
        const int* sp = g_srcs + v * CAP;

        int s0 = 0, s1 = 0;
        float e0 = -CUDART_INF_F, e1 = -CUDART_INF_F;
        if (lane < cnt) {
            s0 = sp[lane];
            float e = g_sv[s0] + dvv;
            e0 = (e > 0.0f) ? e : LRELU_ALPHA * e;
        }
        if (lane + 32 < cnt) {
            s1 = sp[lane + 32];
            float e = g_sv[s1] + dvv;
            e1 = (e > 0.0f) ? e : LRELU_ALPHA * e;
        }

        float m = fmaxf(e0, e1);
#pragma unroll
        for (int off = 16; off; off >>= 1)
            m = fmaxf(m, __shfl_xor_sync(0xffffffffu, m, off));

        float ex0 = (lane < cnt)      ? __expf(e0 - m) : 0.0f;
        float ex1 = (lane + 32 < cnt) ? __expf(e1 - m) : 0.0f;
        float sum = ex0 + ex1;
#pragma unroll
        for (int off = 16; off; off >>= 1)
            sum += __shfl_xor_sync(0xffffffffu, sum, off);
        const float inv = 1.0f / sum;

        stage[warp][lane]      = make_float2(ex0 * inv, __int_as_float(s0));
        stage[warp][lane + 32] = make_float2(ex1 * inv, __int_as_float(s1));
        __syncwarp();

        const uint2* Whh = (const uint2*)g_Whh;   // 8B = 4 halfs per lane
        int i = 0;
        for (; i + 4 <= cnt; i += 4) {
            float2 p0 = stage[warp][i + 0];
            float2 p1 = stage[warp][i + 1];
            float2 p2 = stage[warp][i + 2];
            float2 p3 = stage[warp][i + 3];
            uint2 u0 = Whh[__float_as_int(p0.y) * 32 + lane];
            uint2 u1 = Whh[__float_as_int(p1.y) * 32 + lane];
            uint2 u2 = Whh[__float_as_int(p2.y) * 32 + lane];
            uint2 u3 = Whh[__float_as_int(p3.y) * 32 + lane];
#define ACC(u, al)                                                         \
            {                                                              \
                float2 lo = __half22float2(*(__half2*)&(u).x);             \
                float2 hi = __half22float2(*(__half2*)&(u).y);             \
                acc.x = fmaf((al), lo.x, acc.x);                           \
                acc.y = fmaf((al), lo.y, acc.y);                           \
                acc.z = fmaf((al), hi.x, acc.z);                           \
                acc.w = fmaf((al), hi.y, acc.w);                           \
            }
            ACC(u0, p0.x) ACC(u1, p1.x) ACC(u2, p2.x) ACC(u3, p3.x)
        }
        for (; i < cnt; i++) {
            float2 p = stage[warp][i];
            uint2 u = Whh[__float_as_int(p.y) * 32 + lane];
            ACC(u, p.x)
        }
#undef ACC
    }

    ((float4*)out)[v * 32 + lane] = acc;
}

// ---------------------------------------------------------------------------
extern "C" void kernel_launch(void* const* d_in, const int* in_sizes, int n_in,
                              void* d_out, int out_size) {
    const float* h   = (const float*)d_in[0];
    const float* W   = (const float*)d_in[1];
    const float* a   = (const float*)d_in[2];
    const int*   src = (const int*)d_in[3];
    const int*   dst = (const int*)d_in[4];
    float*       out = (float*)d_out;

    k_reset<<<(Nn / 4 + 127) / 128, 128>>>();
    k_build<<<GEMM_BLOCKS + SCAT_BLOCKS, 256>>>(h, W, a,
                                                (const int4*)src, (const int4*)dst);
    k_node <<<(Nn + 7) / 8, 256>>>(h, out);
}